// round 14
// baseline (speedup 1.0000x reference)
#include <cuda_runtime.h>

// Problem constants (from reference)
#define B        4096
#define N_ELEM   2048
#define N_NODES  1024
#define E2       4096
#define G        4                     // batches per group
#define NGROUPS  (B / G)               // 1024 groups
#define NBLK     152                   // 1 CTA/SM, persistent
#define THREADS  512                   // 2 (degree-sorted) nodes per thread

// __device__ scratch (16B-aligned for cp.async.bulk sources).
__device__ __align__(16) float4 g_csr[E2 + 4];      // + dummy zero records
__device__ __align__(16) int    g_off[N_NODES + 4];
__device__ int   g_perm[E2];            // slot -> original edge index
__device__ int   g_nodeof[N_NODES];     // sorted rank -> node id
__device__ float g_part[NBLK];
__device__ int   g_ctr = 0;

// Dynamic smem layout (bytes):
#define OFF_CSR    0                    // float4[E2+4] = 65600 (reserve 65792)
#define OFF_AXIAL  65792                // float4[2048] = 32768
#define OFF_BUF0   98560                // 64K: [EA g0..g3 | e g0..g3]
#define OFF_BUF1   164096               // 64K
#define SMEM_BYTES 229632               // <= 232448 limit

#define CSR_BYTES   ((E2 + 4) * 16)      // 65600
#define GRP_BYTES   (2 * G * N_ELEM * 4) // 65536

__device__ __forceinline__ unsigned smem_u32(const void* p) {
    return (unsigned)__cvta_generic_to_shared(p);
}
__device__ __forceinline__ void mbar_init(unsigned mbar, unsigned count) {
    asm volatile("mbarrier.init.shared.b64 [%0], %1;" :: "r"(mbar), "r"(count) : "memory");
}
__device__ __forceinline__ void mbar_expect_tx(unsigned mbar, unsigned bytes) {
    asm volatile("mbarrier.arrive.expect_tx.shared.b64 _, [%0], %1;"
                 :: "r"(mbar), "r"(bytes) : "memory");
}
__device__ __forceinline__ void mbar_wait(unsigned mbar, unsigned parity) {
    asm volatile(
        "{\n\t.reg .pred P;\n\t"
        "W%=:\n\t"
        "mbarrier.try_wait.parity.acquire.cta.shared::cta.b64 P, [%0], %1, 0x989680;\n\t"
        "@!P bra W%=;\n\t}"
        :: "r"(mbar), "r"(parity) : "memory");
}
__device__ __forceinline__ void bulk_g2s(unsigned dst_smem, const void* src,
                                         unsigned bytes, unsigned mbar) {
    asm volatile(
        "cp.async.bulk.shared::cta.global.mbarrier::complete_tx::bytes [%0], [%1], %2, [%3];"
        :: "r"(dst_smem), "l"(src), "r"(bytes), "r"(mbar) : "memory");
}

// ---------------------------------------------------------------------------
// Plan: deterministic CSR permutation + offsets + degree-sorted node ranks
// (counting sort by degree, per-bucket id sort -> deterministic). One block.
// ---------------------------------------------------------------------------
__global__ __launch_bounds__(N_NODES)
void nel_plan_kernel(const int* __restrict__ node_ids) {
    __shared__ int s_beg[N_NODES];
    __shared__ int s_cur[N_NODES];
    __shared__ int s_idx[E2];
    __shared__ int s_sorted[N_NODES];
    __shared__ int s_wsum[32];
    __shared__ int s_dhist[64];
    __shared__ int s_dbase[64];
    __shared__ int s_dcur[64];
    const int tid  = threadIdx.x;
    const int lane = tid & 31;
    const int wrp  = tid >> 5;

    // 1. histogram
    s_beg[tid] = 0;
    if (tid < 64) s_dhist[tid] = 0;
    __syncthreads();
    #pragma unroll
    for (int i = tid; i < E2; i += N_NODES)
        atomicAdd(&s_beg[node_ids[i]], 1);
    __syncthreads();

    // 2. exclusive scan via warp shuffles
    const int cnt = s_beg[tid];
    int v = cnt;
    #pragma unroll
    for (int o = 1; o < 32; o <<= 1) {
        int t = __shfl_up_sync(0xffffffffu, v, o);
        if (lane >= o) v += t;
    }
    if (lane == 31) s_wsum[wrp] = v;
    __syncthreads();
    if (wrp == 0) {
        int w = s_wsum[lane];
        #pragma unroll
        for (int o = 1; o < 32; o <<= 1) {
            int t = __shfl_up_sync(0xffffffffu, w, o);
            if (lane >= o) w += t;
        }
        s_wsum[lane] = w - s_wsum[lane];
    }
    __syncthreads();
    const int excl = v - cnt + s_wsum[wrp];
    s_beg[tid] = excl;
    s_cur[tid] = excl;
    const int deg = (cnt < 63) ? cnt : 63;
    atomicAdd(&s_dhist[deg], 1);
    __syncthreads();

    // 3. scatter edge indices into bins
    #pragma unroll
    for (int i = tid; i < E2; i += N_NODES) {
        int pos = atomicAdd(&s_cur[node_ids[i]], 1);
        s_idx[pos] = i;
    }
    __syncthreads();

    // 4. per-bin insertion sort -> deterministic edge order
    {
        const int beg = s_beg[tid], end = s_cur[tid];
        for (int a = beg + 1; a < end; a++) {
            int key = s_idx[a];
            int p = a - 1;
            while (p >= beg && s_idx[p] > key) { s_idx[p + 1] = s_idx[p]; p--; }
            s_idx[p + 1] = key;
        }
    }

    // 4b. degree-descending bucket bases (64-step serial scan; cheap)
    if (tid == 0) {
        int running = 0;
        for (int d = 63; d >= 0; d--) {
            s_dbase[d] = running;
            s_dcur[d]  = running;
            running   += s_dhist[d];
        }
    }
    __syncthreads();

    // 4c. place node ids into degree buckets (order arbitrary here)
    {
        int pos = atomicAdd(&s_dcur[deg], 1);
        s_sorted[pos] = tid;
    }
    __syncthreads();

    // 4d. per-bucket insertion sort by id -> fully deterministic ranks
    if (tid < 64) {
        const int b = s_dbase[tid];
        const int e = b + s_dhist[tid];
        for (int a = b + 1; a < e; a++) {
            int key = s_sorted[a];
            int p = a - 1;
            while (p >= b && s_sorted[p] > key) { s_sorted[p + 1] = s_sorted[p]; p--; }
            s_sorted[p + 1] = key;
        }
    }
    __syncthreads();

    // 5. write outputs
    g_off[tid]    = s_beg[tid];
    g_nodeof[tid] = s_sorted[tid];
    if (tid == 0) {
        g_off[N_NODES] = E2; g_off[N_NODES + 1] = E2;
        g_off[N_NODES + 2] = E2; g_off[N_NODES + 3] = E2;
    }
    #pragma unroll
    for (int i = tid; i < E2; i += N_NODES)
        g_perm[i] = s_idx[i];
}

// ---------------------------------------------------------------------------
// Materialize: write fused CSR records in parallel (many blocks).
// ---------------------------------------------------------------------------
__global__ __launch_bounds__(256)
void nel_mat_kernel(const int* __restrict__ elem_ids,
                    const float* __restrict__ vecs) {
    int i = blockIdx.x * 256 + threadIdx.x;
    if (i < E2) {
        int idx = g_perm[i];
        float4 rec;
        rec.x = __int_as_float(elem_ids[idx]);
        rec.y = vecs[2 * idx];
        rec.z = vecs[2 * idx + 1];
        rec.w = 0.f;
        g_csr[i] = rec;
    } else if (i < E2 + 4) {
        g_csr[i] = make_float4(__int_as_float(0), 0.f, 0.f, 0.f);  // dummy
    }
}

// ---------------------------------------------------------------------------
// Main: 152 persistent blocks (1/SM), 512 threads, G=4 batches per group.
// Thread t handles degree-sorted nodes nodeof[t], nodeof[t+512] -> the
// warp-uniform gather bound is ~warp-mean degree instead of warp-max.
// ---------------------------------------------------------------------------
__global__ __launch_bounds__(THREADS, 1)
void nel_main_kernel(const float* __restrict__ EA,
                     const float* __restrict__ e,
                     const float* __restrict__ q,
                     const float* __restrict__ r,
                     float* __restrict__ out) {
    extern __shared__ unsigned char dyn[];
    float4* s_csr   = (float4*)(dyn + OFF_CSR);
    float4* s_axial = (float4*)(dyn + OFF_AXIAL);
    float*  s_buf0  = (float*) (dyn + OFF_BUF0);
    float*  s_buf1  = (float*) (dyn + OFF_BUF1);
    __shared__ __align__(8) unsigned long long s_mbar[2];
    __shared__ float s_warp[THREADS / 32];
    __shared__ int   s_islast;

    const int tid = threadIdx.x;
    const int g0  = blockIdx.x;
    const int cnt = (NGROUPS - g0 + NBLK - 1) / NBLK;
    const unsigned mb0 = smem_u32(&s_mbar[0]);
    const unsigned mb1 = smem_u32(&s_mbar[1]);

    if (tid == 0) { mbar_init(mb0, 1); mbar_init(mb1, 1); }
    __syncthreads();

    // degree-sorted node assignment (batch-invariant, from L2)
    const int n0 = __ldg(&g_nodeof[tid]);
    const int n1 = __ldg(&g_nodeof[tid + THREADS]);
    const int beg0 = __ldg(&g_off[n0]);
    const int len0 = __ldg(&g_off[n0 + 1]) - beg0;
    const int beg1 = __ldg(&g_off[n1]);
    const int len1 = __ldg(&g_off[n1 + 1]) - beg1;
    // warp-uniform iteration bounds (now ~= warp-mean degree)
    int m0 = len0, m1 = len1;
    #pragma unroll
    for (int o = 16; o > 0; o >>= 1) {
        m0 = max(m0, __shfl_xor_sync(0xffffffffu, m0, o));
        m1 = max(m1, __shfl_xor_sync(0xffffffffu, m1, o));
    }

    // --- prologue: CSR + group 0 on mb0, group 1 on mb1 ---
    if (tid == 0) {
        {
            int grp = g0;
            mbar_expect_tx(mb0, CSR_BYTES + GRP_BYTES);
            bulk_g2s(smem_u32(s_csr), g_csr, CSR_BYTES, mb0);
            bulk_g2s(smem_u32(s_buf0),
                     EA + (size_t)grp * G * N_ELEM, G * N_ELEM * 4, mb0);
            bulk_g2s(smem_u32(s_buf0 + G * N_ELEM),
                     e  + (size_t)grp * G * N_ELEM, G * N_ELEM * 4, mb0);
        }
        if (cnt > 1) {
            int grp = g0 + NBLK;
            mbar_expect_tx(mb1, GRP_BYTES);
            bulk_g2s(smem_u32(s_buf1),
                     EA + (size_t)grp * G * N_ELEM, G * N_ELEM * 4, mb1);
            bulk_g2s(smem_u32(s_buf1 + G * N_ELEM),
                     e  + (size_t)grp * G * N_ELEM, G * N_ELEM * 4, mb1);
        }
    }

    float acc = 0.f;
    unsigned ph0 = 0, ph1 = 0;

    for (int k = 0; k < cnt; k++) {
        const int grp  = g0 + k * NBLK;
        const int bsel = k & 1;
        float* buf = bsel ? s_buf1 : s_buf0;
        const unsigned mb = bsel ? mb1 : mb0;

        // --- early-issue q/r loads (permuted; L2 absorbs scatter) ---
        const float2* q2 = (const float2*)(q + (size_t)grp * G * N_NODES * 2);
        const float2* r2 = (const float2*)(r + (size_t)grp * G * N_NODES * 2);
        float2 qq0[G], rr0[G], qq1[G], rr1[G];
        #pragma unroll
        for (int g = 0; g < G; g++) {
            qq0[g] = __ldg(&q2[g * N_NODES + n0]);
            rr0[g] = __ldg(&r2[g * N_NODES + n0]);
            qq1[g] = __ldg(&q2[g * N_NODES + n1]);
            rr1[g] = __ldg(&r2[g * N_NODES + n1]);
        }

        if (bsel) { mbar_wait(mb, ph1); ph1 ^= 1; }
        else      { mbar_wait(mb, ph0); ph0 ^= 1; }

        // --- build axial4[i] = {EA_g*e_g} for g=0..3 ---
        #pragma unroll
        for (int i = tid; i < N_ELEM; i += THREADS) {
            float4 a;
            a.x = buf[0 * N_ELEM + i] * buf[(G + 0) * N_ELEM + i];
            a.y = buf[1 * N_ELEM + i] * buf[(G + 1) * N_ELEM + i];
            a.z = buf[2 * N_ELEM + i] * buf[(G + 2) * N_ELEM + i];
            a.w = buf[3 * N_ELEM + i] * buf[(G + 3) * N_ELEM + i];
            s_axial[i] = a;
        }
        __syncthreads();   // axial ready; buf free for refill

        // --- refill this buffer with group k+2 (overlaps gather) ---
        if (tid == 0 && k + 2 < cnt) {
            int ng = g0 + (k + 2) * NBLK;
            mbar_expect_tx(mb, GRP_BYTES);
            bulk_g2s(smem_u32(buf),
                     EA + (size_t)ng * G * N_ELEM, G * N_ELEM * 4, mb);
            bulk_g2s(smem_u32(buf + G * N_ELEM),
                     e  + (size_t)ng * G * N_ELEM, G * N_ELEM * 4, mb);
        }

        // --- gather node 0: warp-uniform bound, unroll-4 predicated ---
        float4 ax0 = make_float4(0.f, 0.f, 0.f, 0.f);
        float4 ay0 = make_float4(0.f, 0.f, 0.f, 0.f);
        for (int c = 0; c < m0; c += 4) {
            #pragma unroll
            for (int u = 0; u < 4; u++) {
                int off = c + u;
                int idx = (off < len0) ? (beg0 + off) : E2;   // dummy if past end
                float4 rec = s_csr[idx];
                float4 a   = s_axial[__float_as_int(rec.x)];
                ax0.x += a.x * rec.y;  ax0.y += a.y * rec.y;
                ax0.z += a.z * rec.y;  ax0.w += a.w * rec.y;
                ay0.x += a.x * rec.z;  ay0.y += a.y * rec.z;
                ay0.z += a.z * rec.z;  ay0.w += a.w * rec.z;
            }
        }
        // --- gather node 1 ---
        float4 ax1 = make_float4(0.f, 0.f, 0.f, 0.f);
        float4 ay1 = make_float4(0.f, 0.f, 0.f, 0.f);
        for (int c = 0; c < m1; c += 4) {
            #pragma unroll
            for (int u = 0; u < 4; u++) {
                int off = c + u;
                int idx = (off < len1) ? (beg1 + off) : E2;
                float4 rec = s_csr[idx];
                float4 a   = s_axial[__float_as_int(rec.x)];
                ax1.x += a.x * rec.y;  ax1.y += a.y * rec.y;
                ax1.z += a.z * rec.y;  ax1.w += a.w * rec.y;
                ay1.x += a.x * rec.z;  ay1.y += a.y * rec.z;
                ay1.z += a.z * rec.z;  ay1.w += a.w * rec.z;
            }
        }

        const float* ax0p = (const float*)&ax0;  const float* ay0p = (const float*)&ay0;
        const float* ax1p = (const float*)&ax1;  const float* ay1p = (const float*)&ay1;
        #pragma unroll
        for (int g = 0; g < G; g++) {
            float dx, dy;
            dx = ax0p[g] - qq0[g].x - rr0[g].x;  dy = ay0p[g] - qq0[g].y - rr0[g].y;
            acc += dx * dx + dy * dy;
            dx = ax1p[g] - qq1[g].x - rr1[g].x;  dy = ay1p[g] - qq1[g].y - rr1[g].y;
            acc += dx * dx + dy * dy;
        }
        __syncthreads();   // axial consumed before next build overwrites it
    }

    // --- block reduce ---
    #pragma unroll
    for (int o = 16; o > 0; o >>= 1)
        acc += __shfl_down_sync(0xffffffffu, acc, o);
    if ((tid & 31) == 0) s_warp[tid >> 5] = acc;
    __syncthreads();
    if (tid == 0) {
        float total = 0.f;
        #pragma unroll
        for (int w = 0; w < THREADS / 32; w++) total += s_warp[w];
        g_part[blockIdx.x] = total;
    }

    // --- last-block finalize (fixed-order double sum -> deterministic) ---
    __threadfence();
    if (tid == 0) {
        int old = atomicAdd(&g_ctr, 1);
        s_islast = (old == (int)gridDim.x - 1) ? 1 : 0;
    }
    __syncthreads();
    if (s_islast) {
        __threadfence();
        double* s_d = (double*)(dyn + OFF_CSR);   // overlay consumed CSR
        double d = 0.0;
        #pragma unroll
        for (int i = tid; i < NBLK; i += THREADS) d += (double)g_part[i];
        s_d[tid] = d;
        __syncthreads();
        #pragma unroll
        for (int s = THREADS / 2; s > 0; s >>= 1) {
            if (tid < s) s_d[tid] += s_d[tid + s];
            __syncthreads();
        }
        if (tid == 0) {
            out[0] = (float)(s_d[0] / ((double)B * (double)N_NODES * 2.0));
            g_ctr = 0;   // reset for next graph replay
        }
    }
}

extern "C" void kernel_launch(void* const* d_in, const int* in_sizes, int n_in,
                              void* d_out, int out_size) {
    const float* EA       = (const float*)d_in[0];
    const float* e        = (const float*)d_in[1];
    const float* q        = (const float*)d_in[2];
    const float* r        = (const float*)d_in[3];
    const float* vecs     = (const float*)d_in[4];
    const int*   node_ids = (const int*)d_in[5];
    const int*   elem_ids = (const int*)d_in[6];
    float* out = (float*)d_out;

    static int configured = 0;
    if (!configured) {
        cudaFuncSetAttribute(nel_main_kernel,
                             cudaFuncAttributeMaxDynamicSharedMemorySize,
                             SMEM_BYTES);
        configured = 1;
    }

    nel_plan_kernel<<<1, N_NODES>>>(node_ids);
    nel_mat_kernel<<<(E2 + 4 + 255) / 256, 256>>>(elem_ids, vecs);
    nel_main_kernel<<<NBLK, THREADS, SMEM_BYTES>>>(EA, e, q, r, out);
}

// round 15
// speedup vs baseline: 10.5182x; 10.5182x over previous
#include <cuda_runtime.h>

// Problem constants (from reference)
#define B        4096
#define N_ELEM   2048
#define N_NODES  1024
#define E2       4096
#define G        4                     // batches per group
#define NGROUPS  (B / G)               // 1024 groups
#define NBLK     152                   // 1 CTA/SM, persistent
#define THREADS  512                   // 2 (degree-sorted) nodes per thread

// __device__ scratch (16B-aligned for cp.async.bulk sources).
__device__ __align__(16) float4 g_csr[E2 + 4];      // + dummy zero records
__device__ __align__(16) int    g_off[N_NODES + 4];
__device__ int   g_nodeof[N_NODES];     // sorted rank -> node id
__device__ float g_part[NBLK];
__device__ int   g_ctr = 0;

// Dynamic smem layout (bytes):
#define OFF_CSR    0                    // float4[E2+4] = 65600 (reserve 65792)
#define OFF_AXIAL  65792                // float4[2048] = 32768
#define OFF_BUF0   98560                // 64K: [EA g0..g3 | e g0..g3]
#define OFF_BUF1   164096               // 64K
#define SMEM_BYTES 229632               // <= 232448 limit

#define CSR_BYTES   ((E2 + 4) * 16)      // 65600
#define GRP_BYTES   (2 * G * N_ELEM * 4) // 65536

__device__ __forceinline__ unsigned smem_u32(const void* p) {
    return (unsigned)__cvta_generic_to_shared(p);
}
__device__ __forceinline__ void mbar_init(unsigned mbar, unsigned count) {
    asm volatile("mbarrier.init.shared.b64 [%0], %1;" :: "r"(mbar), "r"(count) : "memory");
}
__device__ __forceinline__ void mbar_expect_tx(unsigned mbar, unsigned bytes) {
    asm volatile("mbarrier.arrive.expect_tx.shared.b64 _, [%0], %1;"
                 :: "r"(mbar), "r"(bytes) : "memory");
}
__device__ __forceinline__ void mbar_wait(unsigned mbar, unsigned parity) {
    asm volatile(
        "{\n\t.reg .pred P;\n\t"
        "W%=:\n\t"
        "mbarrier.try_wait.parity.acquire.cta.shared::cta.b64 P, [%0], %1, 0x989680;\n\t"
        "@!P bra W%=;\n\t}"
        :: "r"(mbar), "r"(parity) : "memory");
}
__device__ __forceinline__ void bulk_g2s(unsigned dst_smem, const void* src,
                                         unsigned bytes, unsigned mbar) {
    asm volatile(
        "cp.async.bulk.shared::cta.global.mbarrier::complete_tx::bytes [%0], [%1], %2, [%3];"
        :: "r"(dst_smem), "l"(src), "r"(bytes), "r"(mbar) : "memory");
}

// ---------------------------------------------------------------------------
// Setup: deterministic CSR + bitonic degree-descending node ranking.
// One block, 1024 threads.
// ---------------------------------------------------------------------------
__global__ __launch_bounds__(N_NODES)
void nel_setup_kernel(const int* __restrict__ node_ids,
                      const int* __restrict__ elem_ids,
                      const float* __restrict__ vecs) {
    __shared__ int s_beg[N_NODES];
    __shared__ int s_cur[N_NODES];
    __shared__ int s_idx[E2];
    __shared__ int s_key[N_NODES];
    __shared__ int s_wsum[32];
    const int tid  = threadIdx.x;
    const int lane = tid & 31;
    const int wrp  = tid >> 5;

    // 1. histogram
    s_beg[tid] = 0;
    __syncthreads();
    #pragma unroll
    for (int i = tid; i < E2; i += N_NODES)
        atomicAdd(&s_beg[node_ids[i]], 1);
    __syncthreads();

    // 2. exclusive scan via warp shuffles
    const int cnt = s_beg[tid];
    int v = cnt;
    #pragma unroll
    for (int o = 1; o < 32; o <<= 1) {
        int t = __shfl_up_sync(0xffffffffu, v, o);
        if (lane >= o) v += t;
    }
    if (lane == 31) s_wsum[wrp] = v;
    __syncthreads();
    if (wrp == 0) {
        int w = s_wsum[lane];
        #pragma unroll
        for (int o = 1; o < 32; o <<= 1) {
            int t = __shfl_up_sync(0xffffffffu, w, o);
            if (lane >= o) w += t;
        }
        s_wsum[lane] = w - s_wsum[lane];
    }
    __syncthreads();
    const int excl = v - cnt + s_wsum[wrp];
    s_beg[tid] = excl;
    s_cur[tid] = excl;
    // unique sort key: degree descending, id ascending tiebreak
    s_key[tid] = ((1023 - min(cnt, 1023)) << 10) | tid;
    __syncthreads();

    // 3. scatter edge indices into bins
    #pragma unroll
    for (int i = tid; i < E2; i += N_NODES) {
        int pos = atomicAdd(&s_cur[node_ids[i]], 1);
        s_idx[pos] = i;
    }
    __syncthreads();

    // 4. per-bin insertion sort -> deterministic edge order (bins are tiny)
    {
        const int beg = s_beg[tid], end = s_cur[tid];
        for (int a = beg + 1; a < end; a++) {
            int key = s_idx[a];
            int p = a - 1;
            while (p >= beg && s_idx[p] > key) { s_idx[p + 1] = s_idx[p]; p--; }
            s_idx[p + 1] = key;
        }
    }

    // 4b. bitonic sort of 1024 unique keys (parallel, ~55 stages)
    __syncthreads();
    for (int kk = 2; kk <= N_NODES; kk <<= 1) {
        for (int j = kk >> 1; j > 0; j >>= 1) {
            int ixj = tid ^ j;
            if (ixj > tid) {
                int a = s_key[tid], b2 = s_key[ixj];
                bool up = ((tid & kk) == 0);
                if ((a > b2) == up) { s_key[tid] = b2; s_key[ixj] = a; }
            }
            __syncthreads();
        }
    }

    // 5. write outputs
    g_off[tid]    = s_beg[tid];
    g_nodeof[tid] = s_key[tid] & 1023;
    if (tid == 0) {
        g_off[N_NODES] = E2; g_off[N_NODES + 1] = E2;
        g_off[N_NODES + 2] = E2; g_off[N_NODES + 3] = E2;
    }
    if (tid < 4)
        g_csr[E2 + tid] = make_float4(__int_as_float(0), 0.f, 0.f, 0.f); // dummy
    #pragma unroll
    for (int i = tid; i < E2; i += N_NODES) {
        int idx = s_idx[i];
        float4 rec;
        rec.x = __int_as_float(elem_ids[idx]);
        rec.y = vecs[2 * idx];
        rec.z = vecs[2 * idx + 1];
        rec.w = 0.f;
        g_csr[i] = rec;
    }
}

// ---------------------------------------------------------------------------
// Main: 152 persistent blocks (1/SM), 512 threads, G=4 batches per group.
// Thread t handles degree-sorted nodes nodeof[t], nodeof[t+512] -> the
// warp-uniform gather bound is ~warp-mean degree instead of warp-max.
// ---------------------------------------------------------------------------
__global__ __launch_bounds__(THREADS, 1)
void nel_main_kernel(const float* __restrict__ EA,
                     const float* __restrict__ e,
                     const float* __restrict__ q,
                     const float* __restrict__ r,
                     float* __restrict__ out) {
    extern __shared__ unsigned char dyn[];
    float4* s_csr   = (float4*)(dyn + OFF_CSR);
    float4* s_axial = (float4*)(dyn + OFF_AXIAL);
    float*  s_buf0  = (float*) (dyn + OFF_BUF0);
    float*  s_buf1  = (float*) (dyn + OFF_BUF1);
    __shared__ __align__(8) unsigned long long s_mbar[2];
    __shared__ float s_warp[THREADS / 32];
    __shared__ int   s_islast;

    const int tid = threadIdx.x;
    const int g0  = blockIdx.x;
    const int cnt = (NGROUPS - g0 + NBLK - 1) / NBLK;
    const unsigned mb0 = smem_u32(&s_mbar[0]);
    const unsigned mb1 = smem_u32(&s_mbar[1]);

    if (tid == 0) { mbar_init(mb0, 1); mbar_init(mb1, 1); }
    __syncthreads();

    // degree-sorted node assignment (batch-invariant, from L2)
    const int n0 = __ldg(&g_nodeof[tid]);
    const int n1 = __ldg(&g_nodeof[tid + THREADS]);
    const int beg0 = __ldg(&g_off[n0]);
    const int len0 = __ldg(&g_off[n0 + 1]) - beg0;
    const int beg1 = __ldg(&g_off[n1]);
    const int len1 = __ldg(&g_off[n1 + 1]) - beg1;
    // warp-uniform iteration bounds (now ~= warp-mean degree)
    int m0 = len0, m1 = len1;
    #pragma unroll
    for (int o = 16; o > 0; o >>= 1) {
        m0 = max(m0, __shfl_xor_sync(0xffffffffu, m0, o));
        m1 = max(m1, __shfl_xor_sync(0xffffffffu, m1, o));
    }

    // --- prologue: CSR + group 0 on mb0, group 1 on mb1 ---
    if (tid == 0) {
        {
            int grp = g0;
            mbar_expect_tx(mb0, CSR_BYTES + GRP_BYTES);
            bulk_g2s(smem_u32(s_csr), g_csr, CSR_BYTES, mb0);
            bulk_g2s(smem_u32(s_buf0),
                     EA + (size_t)grp * G * N_ELEM, G * N_ELEM * 4, mb0);
            bulk_g2s(smem_u32(s_buf0 + G * N_ELEM),
                     e  + (size_t)grp * G * N_ELEM, G * N_ELEM * 4, mb0);
        }
        if (cnt > 1) {
            int grp = g0 + NBLK;
            mbar_expect_tx(mb1, GRP_BYTES);
            bulk_g2s(smem_u32(s_buf1),
                     EA + (size_t)grp * G * N_ELEM, G * N_ELEM * 4, mb1);
            bulk_g2s(smem_u32(s_buf1 + G * N_ELEM),
                     e  + (size_t)grp * G * N_ELEM, G * N_ELEM * 4, mb1);
        }
    }

    float acc = 0.f;
    unsigned ph0 = 0, ph1 = 0;

    for (int k = 0; k < cnt; k++) {
        const int grp  = g0 + k * NBLK;
        const int bsel = k & 1;
        float* buf = bsel ? s_buf1 : s_buf0;
        const unsigned mb = bsel ? mb1 : mb0;

        // --- early-issue q/r loads (permuted; L2 absorbs scatter) ---
        const float2* q2 = (const float2*)(q + (size_t)grp * G * N_NODES * 2);
        const float2* r2 = (const float2*)(r + (size_t)grp * G * N_NODES * 2);
        float2 qq0[G], rr0[G], qq1[G], rr1[G];
        #pragma unroll
        for (int g = 0; g < G; g++) {
            qq0[g] = __ldg(&q2[g * N_NODES + n0]);
            rr0[g] = __ldg(&r2[g * N_NODES + n0]);
            qq1[g] = __ldg(&q2[g * N_NODES + n1]);
            rr1[g] = __ldg(&r2[g * N_NODES + n1]);
        }

        if (bsel) { mbar_wait(mb, ph1); ph1 ^= 1; }
        else      { mbar_wait(mb, ph0); ph0 ^= 1; }

        // --- build axial4[i] = {EA_g*e_g} for g=0..3 ---
        #pragma unroll
        for (int i = tid; i < N_ELEM; i += THREADS) {
            float4 a;
            a.x = buf[0 * N_ELEM + i] * buf[(G + 0) * N_ELEM + i];
            a.y = buf[1 * N_ELEM + i] * buf[(G + 1) * N_ELEM + i];
            a.z = buf[2 * N_ELEM + i] * buf[(G + 2) * N_ELEM + i];
            a.w = buf[3 * N_ELEM + i] * buf[(G + 3) * N_ELEM + i];
            s_axial[i] = a;
        }
        __syncthreads();   // axial ready; buf free for refill

        // --- refill this buffer with group k+2 (overlaps gather) ---
        if (tid == 0 && k + 2 < cnt) {
            int ng = g0 + (k + 2) * NBLK;
            mbar_expect_tx(mb, GRP_BYTES);
            bulk_g2s(smem_u32(buf),
                     EA + (size_t)ng * G * N_ELEM, G * N_ELEM * 4, mb);
            bulk_g2s(smem_u32(buf + G * N_ELEM),
                     e  + (size_t)ng * G * N_ELEM, G * N_ELEM * 4, mb);
        }

        // --- gather node 0: warp-uniform bound, unroll-4 predicated ---
        float4 ax0 = make_float4(0.f, 0.f, 0.f, 0.f);
        float4 ay0 = make_float4(0.f, 0.f, 0.f, 0.f);
        for (int c = 0; c < m0; c += 4) {
            #pragma unroll
            for (int u = 0; u < 4; u++) {
                int off = c + u;
                int idx = (off < len0) ? (beg0 + off) : E2;   // dummy if past end
                float4 rec = s_csr[idx];
                float4 a   = s_axial[__float_as_int(rec.x)];
                ax0.x += a.x * rec.y;  ax0.y += a.y * rec.y;
                ax0.z += a.z * rec.y;  ax0.w += a.w * rec.y;
                ay0.x += a.x * rec.z;  ay0.y += a.y * rec.z;
                ay0.z += a.z * rec.z;  ay0.w += a.w * rec.z;
            }
        }
        // --- gather node 1 ---
        float4 ax1 = make_float4(0.f, 0.f, 0.f, 0.f);
        float4 ay1 = make_float4(0.f, 0.f, 0.f, 0.f);
        for (int c = 0; c < m1; c += 4) {
            #pragma unroll
            for (int u = 0; u < 4; u++) {
                int off = c + u;
                int idx = (off < len1) ? (beg1 + off) : E2;
                float4 rec = s_csr[idx];
                float4 a   = s_axial[__float_as_int(rec.x)];
                ax1.x += a.x * rec.y;  ax1.y += a.y * rec.y;
                ax1.z += a.z * rec.y;  ax1.w += a.w * rec.y;
                ay1.x += a.x * rec.z;  ay1.y += a.y * rec.z;
                ay1.z += a.z * rec.z;  ay1.w += a.w * rec.z;
            }
        }

        const float* ax0p = (const float*)&ax0;  const float* ay0p = (const float*)&ay0;
        const float* ax1p = (const float*)&ax1;  const float* ay1p = (const float*)&ay1;
        #pragma unroll
        for (int g = 0; g < G; g++) {
            float dx, dy;
            dx = ax0p[g] - qq0[g].x - rr0[g].x;  dy = ay0p[g] - qq0[g].y - rr0[g].y;
            acc += dx * dx + dy * dy;
            dx = ax1p[g] - qq1[g].x - rr1[g].x;  dy = ay1p[g] - qq1[g].y - rr1[g].y;
            acc += dx * dx + dy * dy;
        }
        __syncthreads();   // axial consumed before next build overwrites it
    }

    // --- block reduce ---
    #pragma unroll
    for (int o = 16; o > 0; o >>= 1)
        acc += __shfl_down_sync(0xffffffffu, acc, o);
    if ((tid & 31) == 0) s_warp[tid >> 5] = acc;
    __syncthreads();
    if (tid == 0) {
        float total = 0.f;
        #pragma unroll
        for (int w = 0; w < THREADS / 32; w++) total += s_warp[w];
        g_part[blockIdx.x] = total;
    }

    // --- last-block finalize (fixed-order double sum -> deterministic) ---
    __threadfence();
    if (tid == 0) {
        int old = atomicAdd(&g_ctr, 1);
        s_islast = (old == (int)gridDim.x - 1) ? 1 : 0;
    }
    __syncthreads();
    if (s_islast) {
        __threadfence();
        double* s_d = (double*)(dyn + OFF_CSR);   // overlay consumed CSR
        double d = 0.0;
        #pragma unroll
        for (int i = tid; i < NBLK; i += THREADS) d += (double)g_part[i];
        s_d[tid] = d;
        __syncthreads();
        #pragma unroll
        for (int s = THREADS / 2; s > 0; s >>= 1) {
            if (tid < s) s_d[tid] += s_d[tid + s];
            __syncthreads();
        }
        if (tid == 0) {
            out[0] = (float)(s_d[0] / ((double)B * (double)N_NODES * 2.0));
            g_ctr = 0;   // reset for next graph replay
        }
    }
}

extern "C" void kernel_launch(void* const* d_in, const int* in_sizes, int n_in,
                              void* d_out, int out_size) {
    const float* EA       = (const float*)d_in[0];
    const float* e        = (const float*)d_in[1];
    const float* q        = (const float*)d_in[2];
    const float* r        = (const float*)d_in[3];
    const float* vecs     = (const float*)d_in[4];
    const int*   node_ids = (const int*)d_in[5];
    const int*   elem_ids = (const int*)d_in[6];
    float* out = (float*)d_out;

    static int configured = 0;
    if (!configured) {
        cudaFuncSetAttribute(nel_main_kernel,
                             cudaFuncAttributeMaxDynamicSharedMemorySize,
                             SMEM_BYTES);
        configured = 1;
    }

    nel_setup_kernel<<<1, N_NODES>>>(node_ids, elem_ids, vecs);
    nel_main_kernel<<<NBLK, THREADS, SMEM_BYTES>>>(EA, e, q, r, out);
}

// round 16
// speedup vs baseline: 14.2762x; 1.3573x over previous
#include <cuda_runtime.h>

// Problem constants (from reference)
#define B        4096
#define N_ELEM   2048
#define N_NODES  1024
#define E2       4096
#define G        4                     // batches per group
#define NGROUPS  (B / G)               // 1024 groups
#define NBLK     152                   // 1 CTA/SM, persistent
#define THREADS  1024                  // 1 node per thread

// __device__ scratch (16B-aligned for cp.async.bulk sources).
__device__ __align__(16) float4 g_csr[E2 + 4];      // + dummy zero records
__device__ __align__(16) int    g_off[N_NODES + 4];
__device__ int   g_perm[E2];            // slot -> original edge index
__device__ float g_part[NBLK];
__device__ int   g_ctr = 0;

// Dynamic smem layout (bytes):
#define OFF_CSR    0                    // float4[E2+4] = 65600 (reserve 65792)
#define OFF_AXIAL  65792                // float4[2048] = 32768
#define OFF_BUF0   98560                // 64K: [EA g0..g3 | e g0..g3]
#define OFF_BUF1   164096               // 64K
#define SMEM_BYTES 229632               // <= 232448 limit

#define CSR_BYTES   ((E2 + 4) * 16)      // 65600
#define GRP_BYTES   (2 * G * N_ELEM * 4) // 65536

__device__ __forceinline__ unsigned smem_u32(const void* p) {
    return (unsigned)__cvta_generic_to_shared(p);
}
__device__ __forceinline__ void mbar_init(unsigned mbar, unsigned count) {
    asm volatile("mbarrier.init.shared.b64 [%0], %1;" :: "r"(mbar), "r"(count) : "memory");
}
__device__ __forceinline__ void mbar_expect_tx(unsigned mbar, unsigned bytes) {
    asm volatile("mbarrier.arrive.expect_tx.shared.b64 _, [%0], %1;"
                 :: "r"(mbar), "r"(bytes) : "memory");
}
__device__ __forceinline__ void mbar_wait(unsigned mbar, unsigned parity) {
    asm volatile(
        "{\n\t.reg .pred P;\n\t"
        "W%=:\n\t"
        "mbarrier.try_wait.parity.acquire.cta.shared::cta.b64 P, [%0], %1, 0x989680;\n\t"
        "@!P bra W%=;\n\t}"
        :: "r"(mbar), "r"(parity) : "memory");
}
__device__ __forceinline__ void bulk_g2s(unsigned dst_smem, const void* src,
                                         unsigned bytes, unsigned mbar) {
    asm volatile(
        "cp.async.bulk.shared::cta.global.mbarrier::complete_tx::bytes [%0], [%1], %2, [%3];"
        :: "r"(dst_smem), "l"(src), "r"(bytes), "r"(mbar) : "memory");
}

// ---------------------------------------------------------------------------
// Plan: deterministic CSR permutation + offsets. One block, 1024 threads.
// ---------------------------------------------------------------------------
__global__ __launch_bounds__(N_NODES)
void nel_plan_kernel(const int* __restrict__ node_ids) {
    __shared__ int s_beg[N_NODES];
    __shared__ int s_cur[N_NODES];
    __shared__ int s_idx[E2];
    __shared__ int s_wsum[32];
    const int tid  = threadIdx.x;
    const int lane = tid & 31;
    const int wrp  = tid >> 5;

    // 1. histogram
    s_beg[tid] = 0;
    __syncthreads();
    #pragma unroll
    for (int i = tid; i < E2; i += N_NODES)
        atomicAdd(&s_beg[node_ids[i]], 1);
    __syncthreads();

    // 2. exclusive scan via warp shuffles
    const int cnt = s_beg[tid];
    int v = cnt;
    #pragma unroll
    for (int o = 1; o < 32; o <<= 1) {
        int t = __shfl_up_sync(0xffffffffu, v, o);
        if (lane >= o) v += t;
    }
    if (lane == 31) s_wsum[wrp] = v;
    __syncthreads();
    if (wrp == 0) {
        int w = s_wsum[lane];
        #pragma unroll
        for (int o = 1; o < 32; o <<= 1) {
            int t = __shfl_up_sync(0xffffffffu, w, o);
            if (lane >= o) w += t;
        }
        s_wsum[lane] = w - s_wsum[lane];
    }
    __syncthreads();
    const int excl = v - cnt + s_wsum[wrp];
    s_beg[tid] = excl;
    s_cur[tid] = excl;
    __syncthreads();

    // 3. scatter edge indices into bins
    #pragma unroll
    for (int i = tid; i < E2; i += N_NODES) {
        int pos = atomicAdd(&s_cur[node_ids[i]], 1);
        s_idx[pos] = i;
    }
    __syncthreads();

    // 4. per-bin insertion sort -> deterministic edge order
    {
        const int beg = s_beg[tid], end = s_cur[tid];
        for (int a = beg + 1; a < end; a++) {
            int key = s_idx[a];
            int p = a - 1;
            while (p >= beg && s_idx[p] > key) { s_idx[p + 1] = s_idx[p]; p--; }
            s_idx[p + 1] = key;
        }
    }
    __syncthreads();

    // 5. write perm + offsets
    g_off[tid] = s_beg[tid];
    if (tid == 0) {
        g_off[N_NODES] = E2; g_off[N_NODES + 1] = E2;
        g_off[N_NODES + 2] = E2; g_off[N_NODES + 3] = E2;
    }
    #pragma unroll
    for (int i = tid; i < E2; i += N_NODES)
        g_perm[i] = s_idx[i];
}

// ---------------------------------------------------------------------------
// Materialize: write fused CSR records in parallel (many blocks).
// ---------------------------------------------------------------------------
__global__ __launch_bounds__(256)
void nel_mat_kernel(const int* __restrict__ elem_ids,
                    const float* __restrict__ vecs) {
    int i = blockIdx.x * 256 + threadIdx.x;
    if (i < E2) {
        int idx = g_perm[i];
        float4 rec;
        rec.x = __int_as_float(elem_ids[idx]);
        rec.y = vecs[2 * idx];
        rec.z = vecs[2 * idx + 1];
        rec.w = 0.f;
        g_csr[i] = rec;
    } else if (i < E2 + 4) {
        g_csr[i] = make_float4(__int_as_float(0), 0.f, 0.f, 0.f);  // dummy
    }
}

// ---------------------------------------------------------------------------
// Main: 152 persistent blocks (1/SM), 1024 threads (32 warps -> occ 50%),
// 1 node per thread, G=4 batches per group. Unroll-4 predicated gather with
// dummy records; TMA double-buffer for EA/e; q/r via coalesced LDG.
// ---------------------------------------------------------------------------
__global__ __launch_bounds__(THREADS, 1)
void nel_main_kernel(const float* __restrict__ EA,
                     const float* __restrict__ e,
                     const float* __restrict__ q,
                     const float* __restrict__ r,
                     float* __restrict__ out) {
    extern __shared__ unsigned char dyn[];
    float4* s_csr   = (float4*)(dyn + OFF_CSR);
    float4* s_axial = (float4*)(dyn + OFF_AXIAL);
    float*  s_buf0  = (float*) (dyn + OFF_BUF0);
    float*  s_buf1  = (float*) (dyn + OFF_BUF1);
    __shared__ __align__(8) unsigned long long s_mbar[2];
    __shared__ float s_warp[THREADS / 32];
    __shared__ int   s_islast;

    const int tid = threadIdx.x;
    const int g0  = blockIdx.x;
    const int cnt = (NGROUPS - g0 + NBLK - 1) / NBLK;
    const unsigned mb0 = smem_u32(&s_mbar[0]);
    const unsigned mb1 = smem_u32(&s_mbar[1]);

    if (tid == 0) { mbar_init(mb0, 1); mbar_init(mb1, 1); }
    __syncthreads();

    // node span for this thread (batch-invariant, from L2)
    const int n   = tid;
    const int beg = __ldg(&g_off[n]);
    const int len = __ldg(&g_off[n + 1]) - beg;
    // warp-uniform iteration bound (hoisted out of the group loop)
    int m = len;
    #pragma unroll
    for (int o = 16; o > 0; o >>= 1)
        m = max(m, __shfl_xor_sync(0xffffffffu, m, o));

    // --- prologue: CSR + group 0 on mb0, group 1 on mb1 ---
    if (tid == 0) {
        {
            int grp = g0;
            mbar_expect_tx(mb0, CSR_BYTES + GRP_BYTES);
            bulk_g2s(smem_u32(s_csr), g_csr, CSR_BYTES, mb0);
            bulk_g2s(smem_u32(s_buf0),
                     EA + (size_t)grp * G * N_ELEM, G * N_ELEM * 4, mb0);
            bulk_g2s(smem_u32(s_buf0 + G * N_ELEM),
                     e  + (size_t)grp * G * N_ELEM, G * N_ELEM * 4, mb0);
        }
        if (cnt > 1) {
            int grp = g0 + NBLK;
            mbar_expect_tx(mb1, GRP_BYTES);
            bulk_g2s(smem_u32(s_buf1),
                     EA + (size_t)grp * G * N_ELEM, G * N_ELEM * 4, mb1);
            bulk_g2s(smem_u32(s_buf1 + G * N_ELEM),
                     e  + (size_t)grp * G * N_ELEM, G * N_ELEM * 4, mb1);
        }
    }

    float acc = 0.f;
    unsigned ph0 = 0, ph1 = 0;

    for (int k = 0; k < cnt; k++) {
        const int grp  = g0 + k * NBLK;
        const int bsel = k & 1;
        float* buf = bsel ? s_buf1 : s_buf0;
        const unsigned mb = bsel ? mb1 : mb0;

        // --- early-issue q/r loads; fold to t=q+r immediately (8 live regs) ---
        const float2* q2 = (const float2*)(q + (size_t)grp * G * N_NODES * 2);
        const float2* r2 = (const float2*)(r + (size_t)grp * G * N_NODES * 2);
        float2 t[G];
        #pragma unroll
        for (int g = 0; g < G; g++) {
            float2 qq = __ldg(&q2[g * N_NODES + n]);
            float2 rr = __ldg(&r2[g * N_NODES + n]);
            t[g] = make_float2(qq.x + rr.x, qq.y + rr.y);
        }

        if (bsel) { mbar_wait(mb, ph1); ph1 ^= 1; }
        else      { mbar_wait(mb, ph0); ph0 ^= 1; }

        // --- build axial4[i] = {EA_g*e_g} for g=0..3 (2 iters/thread) ---
        #pragma unroll
        for (int i = tid; i < N_ELEM; i += THREADS) {
            float4 a;
            a.x = buf[0 * N_ELEM + i] * buf[(G + 0) * N_ELEM + i];
            a.y = buf[1 * N_ELEM + i] * buf[(G + 1) * N_ELEM + i];
            a.z = buf[2 * N_ELEM + i] * buf[(G + 2) * N_ELEM + i];
            a.w = buf[3 * N_ELEM + i] * buf[(G + 3) * N_ELEM + i];
            s_axial[i] = a;
        }
        __syncthreads();   // axial ready; buf free for refill

        // --- refill this buffer with group k+2 (overlaps gather) ---
        if (tid == 0 && k + 2 < cnt) {
            int ng = g0 + (k + 2) * NBLK;
            mbar_expect_tx(mb, GRP_BYTES);
            bulk_g2s(smem_u32(buf),
                     EA + (size_t)ng * G * N_ELEM, G * N_ELEM * 4, mb);
            bulk_g2s(smem_u32(buf + G * N_ELEM),
                     e  + (size_t)ng * G * N_ELEM, G * N_ELEM * 4, mb);
        }

        // --- gather: warp-uniform bound, unroll-4 predicated ---
        float4 ax = make_float4(0.f, 0.f, 0.f, 0.f);
        float4 ay = make_float4(0.f, 0.f, 0.f, 0.f);
        for (int c = 0; c < m; c += 4) {
            #pragma unroll
            for (int u = 0; u < 4; u++) {
                int off = c + u;
                int idx = (off < len) ? (beg + off) : E2;     // dummy if past end
                float4 rec = s_csr[idx];
                float4 a   = s_axial[__float_as_int(rec.x)];
                ax.x += a.x * rec.y;  ax.y += a.y * rec.y;
                ax.z += a.z * rec.y;  ax.w += a.w * rec.y;
                ay.x += a.x * rec.z;  ay.y += a.y * rec.z;
                ay.z += a.z * rec.z;  ay.w += a.w * rec.z;
            }
        }

        const float* axp = (const float*)&ax;
        const float* ayp = (const float*)&ay;
        #pragma unroll
        for (int g = 0; g < G; g++) {
            float dx = axp[g] - t[g].x;
            float dy = ayp[g] - t[g].y;
            acc += dx * dx + dy * dy;
        }
        __syncthreads();   // axial consumed before next build overwrites it
    }

    // --- block reduce ---
    #pragma unroll
    for (int o = 16; o > 0; o >>= 1)
        acc += __shfl_down_sync(0xffffffffu, acc, o);
    if ((tid & 31) == 0) s_warp[tid >> 5] = acc;
    __syncthreads();
    if (tid == 0) {
        float total = 0.f;
        #pragma unroll
        for (int w = 0; w < THREADS / 32; w++) total += s_warp[w];
        g_part[blockIdx.x] = total;
    }

    // --- last-block finalize (fixed-order double sum -> deterministic) ---
    __threadfence();
    if (tid == 0) {
        int old = atomicAdd(&g_ctr, 1);
        s_islast = (old == (int)gridDim.x - 1) ? 1 : 0;
    }
    __syncthreads();
    if (s_islast) {
        __threadfence();
        double* s_d = (double*)(dyn + OFF_CSR);   // overlay consumed CSR
        double d = 0.0;
        #pragma unroll
        for (int i = tid; i < NBLK; i += THREADS) d += (double)g_part[i];
        s_d[tid] = d;
        __syncthreads();
        #pragma unroll
        for (int s = THREADS / 2; s > 0; s >>= 1) {
            if (tid < s) s_d[tid] += s_d[tid + s];
            __syncthreads();
        }
        if (tid == 0) {
            out[0] = (float)(s_d[0] / ((double)B * (double)N_NODES * 2.0));
            g_ctr = 0;   // reset for next graph replay
        }
    }
}

extern "C" void kernel_launch(void* const* d_in, const int* in_sizes, int n_in,
                              void* d_out, int out_size) {
    const float* EA       = (const float*)d_in[0];
    const float* e        = (const float*)d_in[1];
    const float* q        = (const float*)d_in[2];
    const float* r        = (const float*)d_in[3];
    const float* vecs     = (const float*)d_in[4];
    const int*   node_ids = (const int*)d_in[5];
    const int*   elem_ids = (const int*)d_in[6];
    float* out = (float*)d_out;

    static int configured = 0;
    if (!configured) {
        cudaFuncSetAttribute(nel_main_kernel,
                             cudaFuncAttributeMaxDynamicSharedMemorySize,
                             SMEM_BYTES);
        configured = 1;
    }

    nel_plan_kernel<<<1, N_NODES>>>(node_ids);
    nel_mat_kernel<<<(E2 + 4 + 255) / 256, 256>>>(elem_ids, vecs);
    nel_main_kernel<<<NBLK, THREADS, SMEM_BYTES>>>(EA, e, q, r, out);
}